// round 2
// baseline (speedup 1.0000x reference)
#include <cuda_runtime.h>
#include <math.h>

#define HID   3072
#define HEADS 24
#define HD    128
#define MLPD  12288
#define RANK  32
#define TXTL  512
#define IMGL  2048
#define L_TOT 2560
#define EPSF  1e-6f

__device__ __align__(16) float g_sv[HID];
__device__ __align__(16) float g_mod[2 * 6 * HID];
__device__ __align__(16) float g_xm[(size_t)L_TOT * HID];
__device__ __align__(16) float g_t[(size_t)L_TOT * RANK];
__device__ __align__(16) float g_t2[(size_t)L_TOT * RANK];
__device__ __align__(16) float g_qkv[(size_t)L_TOT * 3 * HID];
__device__ __align__(16) float g_q[(size_t)L_TOT * HID];
__device__ __align__(16) float g_k[(size_t)L_TOT * HID];
__device__ __align__(16) float g_v[(size_t)L_TOT * HID];
__device__ __align__(16) float g_attn[(size_t)L_TOT * HID];
__device__ __align__(16) float g_x1[(size_t)L_TOT * HID];
__device__ __align__(16) float g_h[(size_t)IMGL * MLPD];

__device__ __forceinline__ void blockReduce2(float& a, float& b, float* sbuf) {
    int lane = threadIdx.x & 31, w = threadIdx.x >> 5;
    int nw = blockDim.x >> 5;
#pragma unroll
    for (int o = 16; o; o >>= 1) {
        a += __shfl_xor_sync(0xffffffffu, a, o);
        b += __shfl_xor_sync(0xffffffffu, b, o);
    }
    if (lane == 0) { sbuf[w] = a; sbuf[nw + w] = b; }
    __syncthreads();
    a = 0.f; b = 0.f;
    for (int i = 0; i < nw; ++i) { a += sbuf[i]; b += sbuf[nw + i]; }
    __syncthreads();
}

__device__ __forceinline__ float gelu_f(float x) {
    float u = 0.7978845608028654f * (x + 0.044715f * x * x * x);
    float e = __expf(2.f * u);
    float th = 1.f - 2.f / (e + 1.f);
    return 0.5f * x * (1.f + th);
}

__global__ void silu_kernel(const float* __restrict__ v, float* __restrict__ o) {
    int i = blockIdx.x * 256 + threadIdx.x;
    if (i < HID) { float x = v[i]; o[i] = x / (1.f + __expf(-x)); }
}

__global__ void __launch_bounds__(128) gemv_mod(const float* __restrict__ w,
                                                const float* __restrict__ b,
                                                const float* __restrict__ sv,
                                                float* __restrict__ o) {
    __shared__ float sbuf[8];
    int n = blockIdx.x;
    const float4* wr = (const float4*)(w + (size_t)n * HID);
    const float4* vv = (const float4*)sv;
    int t = threadIdx.x;
    float s = 0.f;
#pragma unroll
    for (int i = 0; i < 6; ++i) {
        float4 a = wr[t + i * 128], c = vv[t + i * 128];
        s += a.x * c.x + a.y * c.y + a.z * c.z + a.w * c.w;
    }
    float dummy = 0.f;
    blockReduce2(s, dummy, sbuf);
    if (t == 0) o[n] = s + b[n];
}

__global__ void __launch_bounds__(256) ln_mod(const float* __restrict__ x,
                                              const float* __restrict__ sh,
                                              const float* __restrict__ sc,
                                              float* __restrict__ o) {
    __shared__ float sbuf[16];
    int row = blockIdx.x, t = threadIdx.x;
    const float4* xr = (const float4*)(x + (size_t)row * HID);
    float4 v[3];
    float s = 0.f, s2 = 0.f;
#pragma unroll
    for (int i = 0; i < 3; ++i) {
        v[i] = xr[t + i * 256];
        s  += v[i].x + v[i].y + v[i].z + v[i].w;
        s2 += v[i].x * v[i].x + v[i].y * v[i].y + v[i].z * v[i].z + v[i].w * v[i].w;
    }
    blockReduce2(s, s2, sbuf);
    float mean = s * (1.f / HID);
    float var  = s2 * (1.f / HID) - mean * mean;
    float rstd = rsqrtf(var + EPSF);
    float4* orow = (float4*)(o + (size_t)row * HID);
    const float4* sh4 = (const float4*)sh;
    const float4* sc4 = (const float4*)sc;
#pragma unroll
    for (int i = 0; i < 3; ++i) {
        int c = t + i * 256;
        float4 scv = sc4[c], shv = sh4[c], r;
        r.x = (v[i].x - mean) * rstd * (1.f + scv.x) + shv.x;
        r.y = (v[i].y - mean) * rstd * (1.f + scv.y) + shv.y;
        r.z = (v[i].z - mean) * rstd * (1.f + scv.z) + shv.z;
        r.w = (v[i].w - mean) * rstd * (1.f + scv.w) + shv.w;
        orow[c] = r;
    }
}

// T[m,r] = sum_k A[m,k]*LD[k,r], R=32
__global__ void __launch_bounds__(256) tgemm(const float* __restrict__ A,
                                             const float* __restrict__ LD,
                                             float* __restrict__ T, int K) {
    __shared__ float As[8][33];
    __shared__ float Ls[32 * 32];
    int t = threadIdx.x, r = t & 31, ml = t >> 5;
    size_t m = (size_t)blockIdx.x * 8 + ml;
    float acc = 0.f;
    for (int k0 = 0; k0 < K; k0 += 32) {
        __syncthreads();
        As[ml][r] = A[m * K + k0 + r];
#pragma unroll
        for (int i = 0; i < 4; ++i) Ls[t + i * 256] = LD[(size_t)k0 * 32 + t + i * 256];
        __syncthreads();
#pragma unroll
        for (int kk = 0; kk < 32; ++kk) acc += As[ml][kk] * Ls[kk * 32 + r];
    }
    T[m * RANK + r] = acc;
}

__device__ __forceinline__ void fma44(float (&c)[4][4], float4 a, float4 b) {
    c[0][0] += a.x * b.x; c[0][1] += a.x * b.y; c[0][2] += a.x * b.z; c[0][3] += a.x * b.w;
    c[1][0] += a.y * b.x; c[1][1] += a.y * b.y; c[1][2] += a.y * b.z; c[1][3] += a.y * b.w;
    c[2][0] += a.z * b.x; c[2][1] += a.z * b.y; c[2][2] += a.z * b.z; c[2][3] += a.z * b.w;
    c[3][0] += a.w * b.x; c[3][1] += a.w * b.y; c[3][2] += a.w * b.z; c[3][3] += a.w * b.w;
}

// C = A(MxK) @ W(NxK)^T + bias + T@LU, MODE1: C = RES + GATE*(.), MODE2: gelu(.)
template <int MODE>
__global__ void __launch_bounds__(256) gemm_tn(const float* __restrict__ A,
                                               const float* __restrict__ W,
                                               const float* __restrict__ bias,
                                               const float* __restrict__ T,
                                               const float* __restrict__ LU,
                                               const float* __restrict__ RES,
                                               const float* __restrict__ GATE,
                                               float* __restrict__ C,
                                               int M, int N, int K) {
    __shared__ float sm[8192];
    float* As = sm;
    float* Bs = sm + 1024;
    int bn = blockIdx.x * 128, bm = blockIdx.y * 128;
    int t = threadIdx.x, tx = t & 15, ty = t >> 4;
    int lr = t >> 1, lc = (t & 1) * 4;
    const float* Ap = A + (size_t)(bm + lr) * K + lc;
    const float* Wp = W + (size_t)(bn + lr) * K + lc;
    float acc[2][2][4][4] = {};

    for (int k0 = 0; k0 < K; k0 += 8) {
        float4 av = *(const float4*)(Ap + k0);
        float4 wv = *(const float4*)(Wp + k0);
        __syncthreads();
        As[(lc + 0) * 128 + lr] = av.x;
        As[(lc + 1) * 128 + lr] = av.y;
        As[(lc + 2) * 128 + lr] = av.z;
        As[(lc + 3) * 128 + lr] = av.w;
        Bs[(lc + 0) * 128 + lr] = wv.x;
        Bs[(lc + 1) * 128 + lr] = wv.y;
        Bs[(lc + 2) * 128 + lr] = wv.z;
        Bs[(lc + 3) * 128 + lr] = wv.w;
        __syncthreads();
#pragma unroll
        for (int k = 0; k < 8; ++k) {
            float4 a0 = *(const float4*)(As + k * 128 + ty * 4);
            float4 a1 = *(const float4*)(As + k * 128 + 64 + ty * 4);
            float4 b0 = *(const float4*)(Bs + k * 128 + tx * 4);
            float4 b1 = *(const float4*)(Bs + k * 128 + 64 + tx * 4);
            fma44(acc[0][0], a0, b0); fma44(acc[0][1], a0, b1);
            fma44(acc[1][0], a1, b0); fma44(acc[1][1], a1, b1);
        }
    }

    __syncthreads();
    float* Ts = sm;          // [128][32]
    float* Ls = sm + 4096;   // [32][128]
    for (int i = t; i < 4096; i += 256) Ts[i] = T[(size_t)bm * 32 + i];
    for (int i = t; i < 4096; i += 256) Ls[i] = LU[(size_t)(i >> 7) * N + bn + (i & 127)];
    __syncthreads();
#pragma unroll 4
    for (int r = 0; r < 32; ++r) {
        float4 u0 = *(const float4*)(Ls + r * 128 + tx * 4);
        float4 u1 = *(const float4*)(Ls + r * 128 + 64 + tx * 4);
#pragma unroll
        for (int rr = 0; rr < 4; ++rr) {
            float a0 = Ts[(ty * 4 + rr) * 32 + r];
            float a1 = Ts[(64 + ty * 4 + rr) * 32 + r];
            acc[0][0][rr][0] += a0 * u0.x; acc[0][0][rr][1] += a0 * u0.y;
            acc[0][0][rr][2] += a0 * u0.z; acc[0][0][rr][3] += a0 * u0.w;
            acc[0][1][rr][0] += a0 * u1.x; acc[0][1][rr][1] += a0 * u1.y;
            acc[0][1][rr][2] += a0 * u1.z; acc[0][1][rr][3] += a0 * u1.w;
            acc[1][0][rr][0] += a1 * u0.x; acc[1][0][rr][1] += a1 * u0.y;
            acc[1][0][rr][2] += a1 * u0.z; acc[1][0][rr][3] += a1 * u0.w;
            acc[1][1][rr][0] += a1 * u1.x; acc[1][1][rr][1] += a1 * u1.y;
            acc[1][1][rr][2] += a1 * u1.z; acc[1][1][rr][3] += a1 * u1.w;
        }
    }

#pragma unroll
    for (int i = 0; i < 2; ++i) {
#pragma unroll
        for (int rr = 0; rr < 4; ++rr) {
            int gm = bm + i * 64 + ty * 4 + rr;
#pragma unroll
            for (int j = 0; j < 2; ++j) {
                int gn = bn + j * 64 + tx * 4;
                float4 bv = *(const float4*)(bias + gn);
                float4 o;
                o.x = acc[i][j][rr][0] + bv.x;
                o.y = acc[i][j][rr][1] + bv.y;
                o.z = acc[i][j][rr][2] + bv.z;
                o.w = acc[i][j][rr][3] + bv.w;
                if (MODE == 2) {
                    o.x = gelu_f(o.x); o.y = gelu_f(o.y);
                    o.z = gelu_f(o.z); o.w = gelu_f(o.w);
                }
                if (MODE == 1) {
                    float4 rv = *(const float4*)(RES + (size_t)gm * N + gn);
                    float4 gv = *(const float4*)(GATE + gn);
                    o.x = rv.x + gv.x * o.x; o.y = rv.y + gv.y * o.y;
                    o.z = rv.z + gv.z * o.z; o.w = rv.w + gv.w * o.w;
                }
                *(float4*)(C + (size_t)gm * N + gn) = o;
            }
        }
    }
}

__global__ void __launch_bounds__(64) rmsrope(const float* __restrict__ qkv,
                                              const float* __restrict__ wq,
                                              const float* __restrict__ wk,
                                              const float* __restrict__ pe, int loff,
                                              float* __restrict__ Q, float* __restrict__ K,
                                              float* __restrict__ V) {
    __shared__ float sbuf[4];
    int row = blockIdx.x, h = blockIdx.y, p = threadIdx.x;
    int l = loff + row;
    const float* base = qkv + (size_t)row * (3 * HID) + h * HD;
    float q0 = base[2 * p], q1 = base[2 * p + 1];
    float k0 = base[HID + 2 * p], k1 = base[HID + 2 * p + 1];
    float sq = q0 * q0 + q1 * q1, sk = k0 * k0 + k1 * k1;
#pragma unroll
    for (int o = 16; o; o >>= 1) {
        sq += __shfl_xor_sync(0xffffffffu, sq, o);
        sk += __shfl_xor_sync(0xffffffffu, sk, o);
    }
    int w = p >> 5;
    if ((p & 31) == 0) { sbuf[w] = sq; sbuf[2 + w] = sk; }
    __syncthreads();
    sq = sbuf[0] + sbuf[1];
    sk = sbuf[2] + sbuf[3];
    float rq = rsqrtf(sq * (1.f / HD) + EPSF);
    float rk = rsqrtf(sk * (1.f / HD) + EPSF);
    q0 *= rq * wq[2 * p]; q1 *= rq * wq[2 * p + 1];
    k0 *= rk * wk[2 * p]; k1 *= rk * wk[2 * p + 1];
    float4 f = ((const float4*)(pe + (size_t)l * 256))[p];
    size_t ob = (size_t)l * HID + h * HD;
    Q[ob + 2 * p]     = f.x * q0 + f.y * q1;
    Q[ob + 2 * p + 1] = f.z * q0 + f.w * q1;
    K[ob + 2 * p]     = f.x * k0 + f.y * k1;
    K[ob + 2 * p + 1] = f.z * k0 + f.w * k1;
    V[ob + 2 * p]     = base[2 * HID + 2 * p];
    V[ob + 2 * p + 1] = base[2 * HID + 2 * p + 1];
}

#define FLASH_SMEM ((3 * 64 * 132 + 64 * 65) * 4)
__global__ void __launch_bounds__(256) flash(const float* __restrict__ Qg,
                                             const float* __restrict__ Kg,
                                             const float* __restrict__ Vg,
                                             float* __restrict__ Og) {
    extern __shared__ float smf[];
    float* Qs = smf;
    float* Ks = Qs + 64 * 132;
    float* Vs = Ks + 64 * 132;
    float* Ps = Vs + 64 * 132;  // [64][65]
    int h = blockIdx.y;
    int qb = blockIdx.x * 64;
    int t = threadIdx.x, r = t >> 2, g = t & 3;
    const float scale = 0.08838834764831845f;

    for (int i = t; i < 64 * 32; i += 256) {
        int rr = i >> 5, c = i & 31;
        float4 qv = ((const float4*)(Qg + (size_t)(qb + rr) * HID + h * HD))[c];
        qv.x *= scale; qv.y *= scale; qv.z *= scale; qv.w *= scale;
        ((float4*)Qs)[rr * 33 + c] = qv;
    }
    float m = -1e30f, lsum = 0.f;
    float4 acc[8];
#pragma unroll
    for (int w = 0; w < 8; ++w) acc[w] = make_float4(0.f, 0.f, 0.f, 0.f);

    for (int kt = 0; kt < L_TOT; kt += 64) {
        __syncthreads();
        for (int i = t; i < 64 * 32; i += 256) {
            int rr = i >> 5, c = i & 31;
            ((float4*)Ks)[rr * 33 + c] = ((const float4*)(Kg + (size_t)(kt + rr) * HID + h * HD))[c];
            ((float4*)Vs)[rr * 33 + c] = ((const float4*)(Vg + (size_t)(kt + rr) * HID + h * HD))[c];
        }
        __syncthreads();

        float s[16];
#pragma unroll
        for (int jj = 0; jj < 16; ++jj) s[jj] = 0.f;
#pragma unroll 8
        for (int d4 = 0; d4 < 32; ++d4) {
            float4 qv = ((const float4*)Qs)[r * 33 + d4];
#pragma unroll
            for (int jj = 0; jj < 16; ++jj) {
                float4 kv = ((const float4*)Ks)[(g + 4 * jj) * 33 + d4];
                s[jj] += qv.x * kv.x + qv.y * kv.y + qv.z * kv.z + qv.w * kv.w;
            }
        }
        float tm = s[0];
#pragma unroll
        for (int jj = 1; jj < 16; ++jj) tm = fmaxf(tm, s[jj]);
        tm = fmaxf(tm, __shfl_xor_sync(0xffffffffu, tm, 1));
        tm = fmaxf(tm, __shfl_xor_sync(0xffffffffu, tm, 2));
        float mn = fmaxf(m, tm);
        float corr = __expf(m - mn);
        float ps = 0.f;
#pragma unroll
        for (int jj = 0; jj < 16; ++jj) {
            float pv = __expf(s[jj] - mn);
            Ps[r * 65 + g + 4 * jj] = pv;
            ps += pv;
        }
        ps += __shfl_xor_sync(0xffffffffu, ps, 1);
        ps += __shfl_xor_sync(0xffffffffu, ps, 2);
        lsum = lsum * corr + ps;
        m = mn;
#pragma unroll
        for (int w = 0; w < 8; ++w) {
            acc[w].x *= corr; acc[w].y *= corr; acc[w].z *= corr; acc[w].w *= corr;
        }
        __syncthreads();
#pragma unroll 4
        for (int j = 0; j < 64; ++j) {
            float pv = Ps[r * 65 + j];
#pragma unroll
            for (int w = 0; w < 8; ++w) {
                float4 vv = ((const float4*)Vs)[j * 33 + g + 4 * w];
                acc[w].x += pv * vv.x; acc[w].y += pv * vv.y;
                acc[w].z += pv * vv.z; acc[w].w += pv * vv.w;
            }
        }
    }
    float inv = 1.f / lsum;
#pragma unroll
    for (int w = 0; w < 8; ++w) {
        float4 o;
        o.x = acc[w].x * inv; o.y = acc[w].y * inv;
        o.z = acc[w].z * inv; o.w = acc[w].w * inv;
        ((float4*)(Og + (size_t)(qb + r) * HID + h * HD))[g + 4 * w] = o;
    }
}

extern "C" void kernel_launch(void* const* d_in, const int* in_sizes, int n_in,
                              void* d_out, int out_size) {
    const float* img     = (const float*)d_in[0];
    const float* txt     = (const float*)d_in[1];
    const float* vec     = (const float*)d_in[2];
    const float* pe      = (const float*)d_in[3];
    const float* mod_w   = (const float*)d_in[4];
    const float* mod_b   = (const float*)d_in[5];
    const float* qkv_w   = (const float*)d_in[6];
    const float* qkv_b   = (const float*)d_in[7];
    const float* qkv_ld  = (const float*)d_in[8];
    const float* qkv_lu  = (const float*)d_in[9];
    const float* rmsq_w  = (const float*)d_in[10];
    const float* rmsk_w  = (const float*)d_in[11];
    const float* proj_w  = (const float*)d_in[12];
    const float* proj_b  = (const float*)d_in[13];
    const float* proj_ld = (const float*)d_in[14];
    const float* proj_lu = (const float*)d_in[15];
    const float* mlp0_w  = (const float*)d_in[16];
    const float* mlp0_b  = (const float*)d_in[17];
    const float* mlp0_ld = (const float*)d_in[18];
    const float* mlp0_lu = (const float*)d_in[19];
    const float* mlp2_w  = (const float*)d_in[20];
    const float* mlp2_b  = (const float*)d_in[21];
    const float* mlp2_ld = (const float*)d_in[22];
    const float* mlp2_lu = (const float*)d_in[23];
    float* out = (float*)d_out;

    float *sv, *mod, *xm, *tb, *tb2, *qkv, *q, *k, *v, *attn, *x1, *hb;
    cudaGetSymbolAddress((void**)&sv,   g_sv);
    cudaGetSymbolAddress((void**)&mod,  g_mod);
    cudaGetSymbolAddress((void**)&xm,   g_xm);
    cudaGetSymbolAddress((void**)&tb,   g_t);
    cudaGetSymbolAddress((void**)&tb2,  g_t2);
    cudaGetSymbolAddress((void**)&qkv,  g_qkv);
    cudaGetSymbolAddress((void**)&q,    g_q);
    cudaGetSymbolAddress((void**)&k,    g_k);
    cudaGetSymbolAddress((void**)&v,    g_v);
    cudaGetSymbolAddress((void**)&attn, g_attn);
    cudaGetSymbolAddress((void**)&x1,   g_x1);
    cudaGetSymbolAddress((void**)&hb,   g_h);

    cudaFuncSetAttribute(flash, cudaFuncAttributeMaxDynamicSharedMemorySize, FLASH_SMEM);

    // vec path
    silu_kernel<<<(HID + 255) / 256, 256>>>(vec, sv);
    gemv_mod<<<2 * 6 * HID, 128>>>(mod_w, mod_b, sv, mod);

    // pre(): s=0 img, s=1 txt
    for (int s = 0; s < 2; ++s) {
        const float* x = s == 0 ? img : txt;
        int M = s == 0 ? IMGL : TXTL;
        int loff = s == 0 ? TXTL : 0;
        const float* mm = mod + (size_t)s * 6 * HID;
        ln_mod<<<M, 256>>>(x, mm + 0 * HID, mm + 1 * HID, xm);
        tgemm<<<M / 8, 256>>>(xm, qkv_ld + (size_t)s * HID * RANK, tb, HID);
        dim3 g1(3 * HID / 128, M / 128);
        gemm_tn<0><<<g1, 256>>>(xm, qkv_w + (size_t)s * 3 * HID * HID,
                                qkv_b + (size_t)s * 3 * HID, tb,
                                qkv_lu + (size_t)s * RANK * 3 * HID,
                                nullptr, nullptr, qkv, M, 3 * HID, HID);
        dim3 g2(M, HEADS);
        rmsrope<<<g2, 64>>>(qkv, rmsq_w + (size_t)s * HD, rmsk_w + (size_t)s * HD,
                            pe, loff, q, k, v);
    }

    // attention over concat L
    dim3 gf(L_TOT / 64, HEADS);
    flash<<<gf, 256, FLASH_SMEM>>>(q, k, v, attn);

    // post(): s=0 img (rows 512..2560), s=1 txt (rows 0..512)
    for (int s = 0; s < 2; ++s) {
        const float* x = s == 0 ? img : txt;
        int M = s == 0 ? IMGL : TXTL;
        int roff = s == 0 ? TXTL : 0;
        const float* a = attn + (size_t)roff * HID;
        const float* mm = mod + (size_t)s * 6 * HID;
        float* outp = out + (size_t)roff * HID;

        // x1 = x + g1 * svdq(a, proj)
        tgemm<<<M / 8, 256>>>(a, proj_ld + (size_t)s * HID * RANK, tb, HID);
        dim3 gp(HID / 128, M / 128);
        gemm_tn<1><<<gp, 256>>>(a, proj_w + (size_t)s * HID * HID,
                                proj_b + (size_t)s * HID, tb,
                                proj_lu + (size_t)s * RANK * HID,
                                x, mm + 2 * HID, x1, M, HID, HID);
        // h = gelu(svdq(ln_mod(x1, sh2, sc2), mlp0))
        ln_mod<<<M, 256>>>(x1, mm + 3 * HID, mm + 4 * HID, xm);
        tgemm<<<M / 8, 256>>>(xm, mlp0_ld + (size_t)s * HID * RANK, tb, HID);
        dim3 gm0(MLPD / 128, M / 128);
        gemm_tn<2><<<gm0, 256>>>(xm, mlp0_w + (size_t)s * MLPD * HID,
                                 mlp0_b + (size_t)s * MLPD, tb,
                                 mlp0_lu + (size_t)s * RANK * MLPD,
                                 nullptr, nullptr, hb, M, MLPD, HID);
        // out = x1 + g2 * svdq(h, mlp2)
        tgemm<<<M / 8, 256>>>(hb, mlp2_ld + (size_t)s * MLPD * RANK, tb2, MLPD);
        dim3 gm2(HID / 128, M / 128);
        gemm_tn<1><<<gm2, 256>>>(hb, mlp2_w + (size_t)s * HID * MLPD,
                                 mlp2_b + (size_t)s * HID, tb2,
                                 mlp2_lu + (size_t)s * RANK * HID,
                                 x1, mm + 5 * HID, outp, M, HID, MLPD);
    }
}

// round 4
// speedup vs baseline: 1.4885x; 1.4885x over previous
#include <cuda_runtime.h>
#include <cuda_bf16.h>
#include <math.h>

#define HID 3072
#define HEADS 24
#define HD 128
#define MLPD 12288
#define RANK 32
#define TXTL 512
#define IMGL 2048
#define L_TOT 2560
#define EPSF 1e-6f

#define QKV_SZ 28311552ULL
#define PRJ_SZ 9437184ULL
#define MLP_SZ 37748736ULL

// ---------------- device scratch ----------------
__device__ __align__(16) float g_sv[HID];
__device__ __align__(16) float g_mod[2 * 6 * HID];
__device__ __align__(16) float g_xm[(size_t)L_TOT * HID];
__device__ __align__(16) float g_t[(size_t)L_TOT * RANK];
__device__ __align__(16) float g_qkv[(size_t)L_TOT * 3 * HID];
__device__ __align__(16) float g_q[(size_t)L_TOT * HID];
__device__ __align__(16) float g_k[(size_t)L_TOT * HID];
__device__ __align__(16) float g_v[(size_t)L_TOT * HID];
__device__ __align__(16) float g_attn[(size_t)L_TOT * HID];
__device__ __align__(16) float g_x1[(size_t)L_TOT * HID];
__device__ __align__(16) float g_h[(size_t)IMGL * MLPD];

__device__ __align__(16) __nv_bfloat16 g_wq_h[2 * QKV_SZ], g_wq_l[2 * QKV_SZ];
__device__ __align__(16) __nv_bfloat16 g_wp_h[2 * PRJ_SZ], g_wp_l[2 * PRJ_SZ];
__device__ __align__(16) __nv_bfloat16 g_w0_h[2 * MLP_SZ], g_w0_l[2 * MLP_SZ];
__device__ __align__(16) __nv_bfloat16 g_w2_h[2 * MLP_SZ], g_w2_l[2 * MLP_SZ];
__device__ __align__(16) __nv_bfloat16 g_a_h[(size_t)IMGL * MLPD], g_a_l[(size_t)IMGL * MLPD];
__device__ __align__(16) __nv_bfloat16 g_t_h[(size_t)L_TOT * RANK], g_t_l[(size_t)L_TOT * RANK];
__device__ __align__(16) __nv_bfloat16 g_lu_h[(size_t)MLPD * RANK], g_lu_l[(size_t)MLPD * RANK];

// ---------------- asm helpers (sm_80-class only) ----------------
__device__ __forceinline__ unsigned smem_u32(const void* p) {
    unsigned a;
    asm("{ .reg .u64 t; cvta.to.shared.u64 t, %1; cvt.u32.u64 %0, t; }" : "=r"(a) : "l"(p));
    return a;
}
__device__ __forceinline__ void ldmx4(unsigned (&r)[4], unsigned a) {
    asm volatile("ldmatrix.sync.aligned.m8n8.x4.shared.b16 {%0,%1,%2,%3}, [%4];"
                 : "=r"(r[0]), "=r"(r[1]), "=r"(r[2]), "=r"(r[3]) : "r"(a));
}
__device__ __forceinline__ void ldmx2(unsigned (&r)[2], unsigned a) {
    asm volatile("ldmatrix.sync.aligned.m8n8.x2.shared.b16 {%0,%1}, [%2];"
                 : "=r"(r[0]), "=r"(r[1]) : "r"(a));
}
__device__ __forceinline__ void mma16816(float (&d)[4], const unsigned (&a)[4], const unsigned (&b)[2]) {
    asm volatile("mma.sync.aligned.m16n8k16.row.col.f32.bf16.bf16.f32 "
                 "{%0,%1,%2,%3},{%4,%5,%6,%7},{%8,%9},{%0,%1,%2,%3};"
                 : "+f"(d[0]), "+f"(d[1]), "+f"(d[2]), "+f"(d[3])
                 : "r"(a[0]), "r"(a[1]), "r"(a[2]), "r"(a[3]), "r"(b[0]), "r"(b[1]));
}
__device__ __forceinline__ void cpa16(unsigned d, const void* s) {
    asm volatile("cp.async.cg.shared.global [%0], [%1], 16;" :: "r"(d), "l"(s));
}
__device__ __forceinline__ void cpcommit() { asm volatile("cp.async.commit_group;"); }
template <int N>
__device__ __forceinline__ void cpwait() { asm volatile("cp.async.wait_group %0;" :: "n"(N)); }

__device__ __forceinline__ float gelu2(float x) {
    float u = 0.7978845608028654f * (x + 0.044715f * x * x * x);
    float e = __expf(2.f * u);
    float th = 1.f - 2.f / (e + 1.f);
    return 0.5f * x * (1.f + th);
}

// ---------------- conversions: fp32 -> bf16 hi/lo (row-major) ----------------
__global__ void __launch_bounds__(256) convHL(const float* __restrict__ src,
                                              __nv_bfloat16* __restrict__ dh,
                                              __nv_bfloat16* __restrict__ dl, size_t n4) {
    size_t idx = (size_t)blockIdx.x * 256 + threadIdx.x;
    if (idx >= n4) return;
    float4 v = ((const float4*)src)[idx];
    float vv[4] = {v.x, v.y, v.z, v.w};
    __nv_bfloat16 h[4], l[4];
#pragma unroll
    for (int i = 0; i < 4; ++i) {
        h[i] = __float2bfloat16(vv[i]);
        l[i] = __float2bfloat16(vv[i] - __bfloat162float(h[i]));
    }
    ((uint2*)dh)[idx] = *(uint2*)h;
    ((uint2*)dl)[idx] = *(uint2*)l;
}

// LU (32 x N) -> [N][32] hi/lo (transpose)
__global__ void __launch_bounds__(256) convLU(const float* __restrict__ LU,
                                              __nv_bfloat16* __restrict__ dh,
                                              __nv_bfloat16* __restrict__ dl, int N) {
    int idx = blockIdx.x * 256 + threadIdx.x;
    if (idx >= N * 32) return;
    int n = idx >> 5, c = idx & 31;
    float v = LU[(size_t)c * N + n];
    __nv_bfloat16 h = __float2bfloat16(v);
    dh[(size_t)n * 32 + c] = h;
    dl[(size_t)n * 32 + c] = __float2bfloat16(v - __bfloat162float(h));
}

// ---------------- bf16 split-precision GEMM (mma.sync) ----------------
// C(MxN) = A @ W^T + T @ LU + bias; MODE1: C = RES + GATE*(.), MODE2: gelu(.)
// smem stage layout (bytes): Ah 0..10239, Al 10240.., Bh 20480.., Bl 40960.. ; stage=61440
#define STG_B 61440
#define GEMM_SMEM (2 * STG_B)

template <int MODE>
__global__ void __launch_bounds__(256) gemm_mma(
    const __nv_bfloat16* __restrict__ Ah, const __nv_bfloat16* __restrict__ Al,
    const __nv_bfloat16* __restrict__ Bh, const __nv_bfloat16* __restrict__ Bl,
    const __nv_bfloat16* __restrict__ Th, const __nv_bfloat16* __restrict__ Tl,
    const __nv_bfloat16* __restrict__ LUh, const __nv_bfloat16* __restrict__ LUl,
    const float* __restrict__ bias, const float* __restrict__ RES,
    const float* __restrict__ GATE, float* __restrict__ C,
    int M, int N, int K) {
    extern __shared__ char sm[];
    unsigned sbase = smem_u32(sm);
    int tid = threadIdx.x, lane = tid & 31, wid = tid >> 5;
    int wm = wid >> 2, wn = wid & 3;
    int bm = blockIdx.x * 128, bn = blockIdx.y * 256;
    int KC = K >> 5, TOT = KC + 1;

    float acc[4][8][4];
#pragma unroll
    for (int a = 0; a < 4; ++a)
#pragma unroll
        for (int b = 0; b < 8; ++b)
#pragma unroll
            for (int c = 0; c < 4; ++c) acc[a][b][c] = 0.f;

#define LOAD_STAGE(cc)                                                                  \
    {                                                                                   \
        int c_ = (cc);                                                                  \
        unsigned sb_ = sbase + (c_ & 1) * STG_B;                                        \
        const __nv_bfloat16 *ah_, *al_, *bh_, *bl_;                                     \
        size_t sa_, sn_; int ko_;                                                       \
        if (c_ < KC) { ah_ = Ah; al_ = Al; bh_ = Bh; bl_ = Bl; sa_ = K; sn_ = K; ko_ = c_ * 32; } \
        else { ah_ = Th; al_ = Tl; bh_ = LUh; bl_ = LUl; sa_ = 32; sn_ = 32; ko_ = 0; } \
        _Pragma("unroll")                                                               \
        for (int j = 0; j < 4; ++j) {                                                   \
            int i = tid + j * 256;                                                      \
            int r = (i >> 2) & 127, seg = i & 3, mat = i >> 9;                          \
            const __nv_bfloat16* s_ = (mat ? al_ : ah_) + (size_t)(bm + r) * sa_ + ko_ + seg * 8; \
            cpa16(sb_ + mat * 10240 + r * 80 + seg * 16, s_);                           \
        }                                                                               \
        _Pragma("unroll")                                                               \
        for (int j = 0; j < 8; ++j) {                                                   \
            int i = tid + j * 256;                                                      \
            int r = (i >> 2) & 255, seg = i & 3, mat = i >> 10;                         \
            const __nv_bfloat16* s_ = (mat ? bl_ : bh_) + (size_t)(bn + r) * sn_ + ko_ + seg * 8; \
            cpa16(sb_ + 20480 + mat * 20480 + r * 80 + seg * 16, s_);                   \
        }                                                                               \
        cpcommit();                                                                     \
    }

    LOAD_STAGE(0);
    for (int c = 0; c < TOT; ++c) {
        if (c + 1 < TOT) { LOAD_STAGE(c + 1); cpwait<1>(); }
        else { cpwait<0>(); }
        __syncthreads();
        unsigned sb = sbase + (c & 1) * STG_B;
#pragma unroll
        for (int s = 0; s < 2; ++s) {
            unsigned ahf[4][4], alf[4][4];
#pragma unroll
            for (int mf = 0; mf < 4; ++mf) {
                unsigned row = wm * 64 + mf * 16 + (lane & 15);
                unsigned off = row * 80 + s * 32 + ((lane >> 4) << 4);
                ldmx4(ahf[mf], sb + off);
                ldmx4(alf[mf], sb + 10240 + off);
            }
#pragma unroll
            for (int nf = 0; nf < 8; ++nf) {
                unsigned brow = wn * 64 + nf * 8 + (lane & 7);
                unsigned boff = 20480 + brow * 80 + s * 32 + (((lane >> 3) & 1) << 4);
                unsigned bh2[2], bl2[2];
                ldmx2(bh2, sb + boff);
                ldmx2(bl2, sb + 20480 + boff);
#pragma unroll
                for (int mf = 0; mf < 4; ++mf) {
                    mma16816(acc[mf][nf], ahf[mf], bh2);
                    mma16816(acc[mf][nf], ahf[mf], bl2);
                    mma16816(acc[mf][nf], alf[mf], bh2);
                }
            }
        }
        __syncthreads();
    }

    // epilogue
#pragma unroll
    for (int nf = 0; nf < 8; ++nf) {
        int gn = bn + wn * 64 + nf * 8 + (lane & 3) * 2;
        float b0 = bias[gn], b1 = bias[gn + 1];
        float g0 = 0.f, g1 = 0.f;
        if (MODE == 1) { g0 = GATE[gn]; g1 = GATE[gn + 1]; }
#pragma unroll
        for (int mf = 0; mf < 4; ++mf) {
            int gm = bm + wm * 64 + mf * 16 + (lane >> 2);
            float v0 = acc[mf][nf][0] + b0, v1 = acc[mf][nf][1] + b1;
            float v2 = acc[mf][nf][2] + b0, v3 = acc[mf][nf][3] + b1;
            if (MODE == 2) { v0 = gelu2(v0); v1 = gelu2(v1); v2 = gelu2(v2); v3 = gelu2(v3); }
            if (MODE == 1) {
                float2 r0 = *(const float2*)&RES[(size_t)gm * N + gn];
                float2 r1 = *(const float2*)&RES[(size_t)(gm + 8) * N + gn];
                v0 = r0.x + g0 * v0; v1 = r0.y + g1 * v1;
                v2 = r1.x + g0 * v2; v3 = r1.y + g1 * v3;
            }
            *(float2*)&C[(size_t)gm * N + gn] = make_float2(v0, v1);
            *(float2*)&C[(size_t)(gm + 8) * N + gn] = make_float2(v2, v3);
        }
    }
}

// ---------------- small kernels ----------------
__device__ __forceinline__ void blockReduce2(float& a, float& b, float* sbuf) {
    int lane = threadIdx.x & 31, w = threadIdx.x >> 5;
    int nw = blockDim.x >> 5;
#pragma unroll
    for (int o = 16; o; o >>= 1) {
        a += __shfl_xor_sync(0xffffffffu, a, o);
        b += __shfl_xor_sync(0xffffffffu, b, o);
    }
    if (lane == 0) { sbuf[w] = a; sbuf[nw + w] = b; }
    __syncthreads();
    a = 0.f; b = 0.f;
    for (int i = 0; i < nw; ++i) { a += sbuf[i]; b += sbuf[nw + i]; }
    __syncthreads();
}

__global__ void silu_kernel(const float* __restrict__ v, float* __restrict__ o) {
    int i = blockIdx.x * 256 + threadIdx.x;
    if (i < HID) { float x = v[i]; o[i] = x / (1.f + __expf(-x)); }
}

__global__ void __launch_bounds__(128) gemv_mod(const float* __restrict__ w,
                                                const float* __restrict__ b,
                                                const float* __restrict__ sv,
                                                float* __restrict__ o) {
    __shared__ float sbuf[8];
    int n = blockIdx.x;
    const float4* wr = (const float4*)(w + (size_t)n * HID);
    const float4* vv = (const float4*)sv;
    int t = threadIdx.x;
    float s = 0.f;
#pragma unroll
    for (int i = 0; i < 6; ++i) {
        float4 a = wr[t + i * 128], c = vv[t + i * 128];
        s += a.x * c.x + a.y * c.y + a.z * c.z + a.w * c.w;
    }
    float dummy = 0.f;
    blockReduce2(s, dummy, sbuf);
    if (t == 0) o[n] = s + b[n];
}

__global__ void __launch_bounds__(256) ln_mod(const float* __restrict__ x,
                                              const float* __restrict__ sh,
                                              const float* __restrict__ sc,
                                              float* __restrict__ o) {
    __shared__ float sbuf[16];
    int row = blockIdx.x, t = threadIdx.x;
    const float4* xr = (const float4*)(x + (size_t)row * HID);
    float4 v[3];
    float s = 0.f, s2 = 0.f;
#pragma unroll
    for (int i = 0; i < 3; ++i) {
        v[i] = xr[t + i * 256];
        s += v[i].x + v[i].y + v[i].z + v[i].w;
        s2 += v[i].x * v[i].x + v[i].y * v[i].y + v[i].z * v[i].z + v[i].w * v[i].w;
    }
    blockReduce2(s, s2, sbuf);
    float mean = s * (1.f / HID);
    float var = s2 * (1.f / HID) - mean * mean;
    float rstd = rsqrtf(var + EPSF);
    float4* orow = (float4*)(o + (size_t)row * HID);
    const float4* sh4 = (const float4*)sh;
    const float4* sc4 = (const float4*)sc;
#pragma unroll
    for (int i = 0; i < 3; ++i) {
        int c = t + i * 256;
        float4 scv = sc4[c], shv = sh4[c], r;
        r.x = (v[i].x - mean) * rstd * (1.f + scv.x) + shv.x;
        r.y = (v[i].y - mean) * rstd * (1.f + scv.y) + shv.y;
        r.z = (v[i].z - mean) * rstd * (1.f + scv.z) + shv.z;
        r.w = (v[i].w - mean) * rstd * (1.f + scv.w) + shv.w;
        orow[c] = r;
    }
}

// T[m,r] = sum_k A[m,k] * LD[k,r], 32 rows/CTA
__global__ void __launch_bounds__(256) tgemm2(const float* __restrict__ A,
                                              const float* __restrict__ LD,
                                              float* __restrict__ T, int K) {
    __shared__ float Ls[64 * 32];
    __shared__ float As[32 * 68];
    int tid = threadIdx.x, lane = tid & 31, w = tid >> 5;
    int bm = blockIdx.x * 32;
    float acc[4] = {0.f, 0.f, 0.f, 0.f};
    for (int k0 = 0; k0 < K; k0 += 64) {
        __syncthreads();
#pragma unroll
        for (int j = 0; j < 8; ++j) {
            int i = tid + j * 256;
            Ls[i] = LD[(size_t)(k0 + (i >> 5)) * 32 + (i & 31)];
        }
#pragma unroll
        for (int j = 0; j < 8; ++j) {
            int i = tid + j * 256;
            int r = i >> 6, c = i & 63;
            As[r * 68 + c] = A[(size_t)(bm + r) * K + k0 + c];
        }
        __syncthreads();
#pragma unroll 8
        for (int kk = 0; kk < 64; ++kk) {
            float ldv = Ls[kk * 32 + lane];
#pragma unroll
            for (int i = 0; i < 4; ++i) acc[i] += As[(w * 4 + i) * 68 + kk] * ldv;
        }
    }
#pragma unroll
    for (int i = 0; i < 4; ++i) T[(size_t)(bm + w * 4 + i) * 32 + lane] = acc[i];
}

__global__ void __launch_bounds__(64) rmsrope(const float* __restrict__ qkv,
                                              const float* __restrict__ wq,
                                              const float* __restrict__ wk,
                                              const float* __restrict__ pe, int loff,
                                              float* __restrict__ Q, float* __restrict__ K,
                                              float* __restrict__ V) {
    __shared__ float sbuf[4];
    int row = blockIdx.x, h = blockIdx.y, p = threadIdx.x;
    int l = loff + row;
    const float* base = qkv + (size_t)row * (3 * HID) + h * HD;
    float q0 = base[2 * p], q1 = base[2 * p + 1];
    float k0 = base[HID + 2 * p], k1 = base[HID + 2 * p + 1];
    float sq = q0 * q0 + q1 * q1, sk = k0 * k0 + k1 * k1;
#pragma unroll
    for (int o = 16; o; o >>= 1) {
        sq += __shfl_xor_sync(0xffffffffu, sq, o);
        sk += __shfl_xor_sync(0xffffffffu, sk, o);
    }
    int w = p >> 5;
    if ((p & 31) == 0) { sbuf[w] = sq; sbuf[2 + w] = sk; }
    __syncthreads();
    sq = sbuf[0] + sbuf[1];
    sk = sbuf[2] + sbuf[3];
    float rq = rsqrtf(sq * (1.f / HD) + EPSF);
    float rk = rsqrtf(sk * (1.f / HD) + EPSF);
    q0 *= rq * wq[2 * p]; q1 *= rq * wq[2 * p + 1];
    k0 *= rk * wk[2 * p]; k1 *= rk * wk[2 * p + 1];
    float4 f = ((const float4*)(pe + (size_t)l * 256))[p];
    size_t ob = (size_t)l * HID + h * HD;
    Q[ob + 2 * p] = f.x * q0 + f.y * q1;
    Q[ob + 2 * p + 1] = f.z * q0 + f.w * q1;
    K[ob + 2 * p] = f.x * k0 + f.y * k1;
    K[ob + 2 * p + 1] = f.z * k0 + f.w * k1;
    V[ob + 2 * p] = base[2 * HID + 2 * p];
    V[ob + 2 * p + 1] = base[2 * HID + 2 * p + 1];
}

#define FLASH_SMEM ((3 * 64 * 132 + 64 * 65) * 4)
__global__ void __launch_bounds__(256) flash(const float* __restrict__ Qg,
                                             const float* __restrict__ Kg,
                                             const float* __restrict__ Vg,
                                             float* __restrict__ Og) {
    extern __shared__ float smf[];
    float* Qs = smf;
    float* Ks = Qs + 64 * 132;
    float* Vs = Ks + 64 * 132;
    float* Ps = Vs + 64 * 132;
    int h = blockIdx.y;
    int qb = blockIdx.x * 64;
    int t = threadIdx.x, r = t >> 2, g = t & 3;
    const float scale = 0.08838834764831845f;

    for (int i = t; i < 64 * 32; i += 256) {
        int rr = i >> 5, c = i & 31;
        float4 qv = ((const float4*)(Qg + (size_t)(qb + rr) * HID + h * HD))[c];
        qv.x *= scale; qv.y *= scale; qv.z *= scale; qv.w *= scale;
        ((float4*)Qs)[rr * 33 + c] = qv;
    }
    float m = -1e30f, lsum = 0.f;
    float4 acc[8];
#pragma unroll
    for (int w = 0; w < 8; ++w) acc[w] = make_float4(0.f, 0.f, 0.f, 0.f);

    for (int kt = 0; kt < L_TOT; kt += 64) {
        __syncthreads();
        for (int i = t; i < 64 * 32; i += 256) {
            int rr = i >> 5, c = i & 31;
            ((float4*)Ks)[rr * 33 + c] = ((const float4*)(Kg + (size_t)(kt + rr) * HID + h * HD))[c];
            ((float4*)Vs)[rr * 33 + c] = ((const float4*)(Vg + (size_t)(kt + rr) * HID + h * HD))[c];
        }
        __syncthreads();

        float s[16];
#pragma unroll
        for (int jj = 0; jj < 16; ++jj) s[jj] = 0.f;
#pragma unroll 8
        for (int d4 = 0; d4 < 32; ++d4) {
            float4 qv = ((const float4*)Qs)[r * 33 + d4];
#pragma unroll
            for (int jj = 0; jj < 16; ++jj) {
                float4 kv = ((const float4*)Ks)[(g + 4 * jj) * 33 + d4];
                s[jj] += qv.x * kv.x + qv.y * kv.y + qv.z * kv.z + qv.w * kv.w;
            }
        }
        float tm = s[0];
#pragma unroll
        for (int jj = 1; jj < 16; ++jj) tm = fmaxf(tm, s[jj]);
        tm = fmaxf(tm, __shfl_xor_sync(0xffffffffu, tm, 1));
        tm = fmaxf(tm, __shfl_xor_sync(0xffffffffu, tm, 2));
        float mn = fmaxf(m, tm);
        float corr = __expf(m - mn);
        float ps = 0.f;
#pragma unroll
        for (int jj = 0; jj < 16; ++jj) {
            float pv = __expf(s[jj] - mn);
            Ps[r * 65 + g + 4 * jj] = pv;
            ps += pv;
        }
        ps += __shfl_xor_sync(0xffffffffu, ps, 1);
        ps += __shfl_xor_sync(0xffffffffu, ps, 2);
        lsum = lsum * corr + ps;
        m = mn;
#pragma unroll
        for (int w = 0; w < 8; ++w) {
            acc[w].x *= corr; acc[w].y *= corr; acc[w].z *= corr; acc[w].w *= corr;
        }
        __syncthreads();
#pragma unroll 4
        for (int j = 0; j < 64; ++j) {
            float pv = Ps[r * 65 + j];
#pragma unroll
            for (int w = 0; w < 8; ++w) {
                float4 vv = ((const float4*)Vs)[j * 33 + g + 4 * w];
                acc[w].x += pv * vv.x; acc[w].y += pv * vv.y;
                acc[w].z += pv * vv.z; acc[w].w += pv * vv.w;
            }
        }
    }
    float inv = 1.f / lsum;
#pragma unroll
    for (int w = 0; w < 8; ++w) {
        float4 o;
        o.x = acc[w].x * inv; o.y = acc[w].y * inv;
        o.z = acc[w].z * inv; o.w = acc[w].w * inv;
        ((float4*)(Og + (size_t)(qb + r) * HID + h * HD))[g + 4 * w] = o;
    }
}

// ---------------- host ----------------
static inline void launch_gemm(int mode, const __nv_bfloat16* Ah, const __nv_bfloat16* Al,
                               const __nv_bfloat16* Bh, const __nv_bfloat16* Bl,
                               const __nv_bfloat16* Th, const __nv_bfloat16* Tl,
                               const __nv_bfloat16* LUh, const __nv_bfloat16* LUl,
                               const float* bias, const float* RES, const float* GATE,
                               float* C, int M, int N, int K) {
    dim3 g(M / 128, N / 256);
    if (mode == 0)
        gemm_mma<0><<<g, 256, GEMM_SMEM>>>(Ah, Al, Bh, Bl, Th, Tl, LUh, LUl, bias, RES, GATE, C, M, N, K);
    else if (mode == 1)
        gemm_mma<1><<<g, 256, GEMM_SMEM>>>(Ah, Al, Bh, Bl, Th, Tl, LUh, LUl, bias, RES, GATE, C, M, N, K);
    else
        gemm_mma<2><<<g, 256, GEMM_SMEM>>>(Ah, Al, Bh, Bl, Th, Tl, LUh, LUl, bias, RES, GATE, C, M, N, K);
}

extern "C" void kernel_launch(void* const* d_in, const int* in_sizes, int n_in,
                              void* d_out, int out_size) {
    const float* img = (const float*)d_in[0];
    const float* txt = (const float*)d_in[1];
    const float* vec = (const float*)d_in[2];
    const float* pe = (const float*)d_in[3];
    const float* mod_w = (const float*)d_in[4];
    const float* mod_b = (const float*)d_in[5];
    const float* qkv_w = (const float*)d_in[6];
    const float* qkv_b = (const float*)d_in[7];
    const float* qkv_ld = (const float*)d_in[8];
    const float* qkv_lu = (const float*)d_in[9];
    const float* rmsq_w = (const float*)d_in[10];
    const float* rmsk_w = (const float*)d_in[11];
    const float* proj_w = (const float*)d_in[12];
    const float* proj_b = (const float*)d_in[13];
    const float* proj_ld = (const float*)d_in[14];
    const float* proj_lu = (const float*)d_in[15];
    const float* mlp0_w = (const float*)d_in[16];
    const float* mlp0_b = (const float*)d_in[17];
    const float* mlp0_ld = (const float*)d_in[18];
    const float* mlp0_lu = (const float*)d_in[19];
    const float* mlp2_w = (const float*)d_in[20];
    const float* mlp2_b = (const float*)d_in[21];
    const float* mlp2_ld = (const float*)d_in[22];
    const float* mlp2_lu = (const float*)d_in[23];
    float* out = (float*)d_out;

    float *sv, *mod, *xm, *tb, *qkv, *q, *k, *v, *attn, *x1, *hb;
    __nv_bfloat16 *wqh, *wql, *wph, *wpl, *w0h, *w0l, *w2h, *w2l;
    __nv_bfloat16 *ah, *al, *th, *tl, *luh, *lul;
    cudaGetSymbolAddress((void**)&sv, g_sv);
    cudaGetSymbolAddress((void**)&mod, g_mod);
    cudaGetSymbolAddress((void**)&xm, g_xm);
    cudaGetSymbolAddress((void**)&tb, g_t);
    cudaGetSymbolAddress((void**)&qkv, g_qkv);
    cudaGetSymbolAddress((void**)&q, g_q);
    cudaGetSymbolAddress((void**)&k, g_k);
    cudaGetSymbolAddress((void**)&v, g_v);
    cudaGetSymbolAddress((void**)&attn, g_attn);
    cudaGetSymbolAddress((void**)&x1, g_x1);
    cudaGetSymbolAddress((void**)&hb, g_h);
    cudaGetSymbolAddress((void**)&wqh, g_wq_h);
    cudaGetSymbolAddress((void**)&wql, g_wq_l);
    cudaGetSymbolAddress((void**)&wph, g_wp_h);
    cudaGetSymbolAddress((void**)&wpl, g_wp_l);
    cudaGetSymbolAddress((void**)&w0h, g_w0_h);
    cudaGetSymbolAddress((void**)&w0l, g_w0_l);
    cudaGetSymbolAddress((void**)&w2h, g_w2_h);
    cudaGetSymbolAddress((void**)&w2l, g_w2_l);
    cudaGetSymbolAddress((void**)&ah, g_a_h);
    cudaGetSymbolAddress((void**)&al, g_a_l);
    cudaGetSymbolAddress((void**)&th, g_t_h);
    cudaGetSymbolAddress((void**)&tl, g_t_l);
    cudaGetSymbolAddress((void**)&luh, g_lu_h);
    cudaGetSymbolAddress((void**)&lul, g_lu_l);

    cudaFuncSetAttribute(flash, cudaFuncAttributeMaxDynamicSharedMemorySize, FLASH_SMEM);
    cudaFuncSetAttribute(gemm_mma<0>, cudaFuncAttributeMaxDynamicSharedMemorySize, GEMM_SMEM);
    cudaFuncSetAttribute(gemm_mma<1>, cudaFuncAttributeMaxDynamicSharedMemorySize, GEMM_SMEM);
    cudaFuncSetAttribute(gemm_mma<2>, cudaFuncAttributeMaxDynamicSharedMemorySize, GEMM_SMEM);

    silu_kernel<<<(HID + 255) / 256, 256>>>(vec, sv);
    gemv_mod<<<2 * 6 * HID, 128>>>(mod_w, mod_b, sv, mod);

    // weight conversions (both streams at once)
    convHL<<<(int)((2 * QKV_SZ / 4 + 255) / 256), 256>>>(qkv_w, wqh, wql, 2 * QKV_SZ / 4);
    convHL<<<(int)((2 * PRJ_SZ / 4 + 255) / 256), 256>>>(proj_w, wph, wpl, 2 * PRJ_SZ / 4);
    convHL<<<(int)((2 * MLP_SZ / 4 + 255) / 256), 256>>>(mlp0_w, w0h, w0l, 2 * MLP_SZ / 4);
    convHL<<<(int)((2 * MLP_SZ / 4 + 255) / 256), 256>>>(mlp2_w, w2h, w2l, 2 * MLP_SZ / 4);

    for (int s = 0; s < 2; ++s) {
        const float* x = s == 0 ? img : txt;
        int M = s == 0 ? IMGL : TXTL;
        int loff = s == 0 ? TXTL : 0;
        const float* mm = mod + (size_t)s * 6 * HID;
        ln_mod<<<M, 256>>>(x, mm + 0 * HID, mm + 1 * HID, xm);
        convHL<<<(M * HID / 4 + 255) / 256, 256>>>(xm, ah, al, (size_t)M * HID / 4);
        tgemm2<<<M / 32, 256>>>(xm, qkv_ld + (size_t)s * HID * RANK, tb, HID);
        convHL<<<(M * RANK / 4 + 255) / 256, 256>>>(tb, th, tl, (size_t)M * RANK / 4);
        convLU<<<(9216 * 32 + 255) / 256, 256>>>(qkv_lu + (size_t)s * RANK * 9216, luh, lul, 9216);
        launch_gemm(0, ah, al, wqh + s * QKV_SZ, wql + s * QKV_SZ, th, tl, luh, lul,
                    qkv_b + (size_t)s * 9216, nullptr, nullptr, qkv, M, 9216, HID);
        dim3 g2(M, HEADS);
        rmsrope<<<g2, 64>>>(qkv, rmsq_w + (size_t)s * HD, rmsk_w + (size_t)s * HD, pe, loff, q, k, v);
    }

    dim3 gf(L_TOT / 64, HEADS);
    flash<<<gf, 256, FLASH_SMEM>>>(q, k, v, attn);

    for (int s = 0; s < 2; ++s) {
        const float* x = s == 0 ? img : txt;
        int M = s == 0 ? IMGL : TXTL;
        int roff = s == 0 ? TXTL : 0;
        const float* a = attn + (size_t)roff * HID;
        const float* mm = mod + (size_t)s * 6 * HID;
        float* outp = out + (size_t)roff * HID;

        convHL<<<(M * HID / 4 + 255) / 256, 256>>>(a, ah, al, (size_t)M * HID / 4);
        tgemm2<<<M / 32, 256>>>(a, proj_ld + (size_t)s * HID * RANK, tb, HID);
        convHL<<<(M * RANK / 4 + 255) / 256, 256>>>(tb, th, tl, (size_t)M * RANK / 4);
        convLU<<<(HID * 32 + 255) / 256, 256>>>(proj_lu + (size_t)s * RANK * HID, luh, lul, HID);
        launch_gemm(1, ah, al, wph + s * PRJ_SZ, wpl + s * PRJ_SZ, th, tl, luh, lul,
                    proj_b + (size_t)s * HID, x, mm + 2 * HID, x1, M, HID, HID);

        ln_mod<<<M, 256>>>(x1, mm + 3 * HID, mm + 4 * HID, xm);
        convHL<<<(M * HID / 4 + 255) / 256, 256>>>(xm, ah, al, (size_t)M * HID / 4);
        tgemm2<<<M / 32, 256>>>(xm, mlp0_ld + (size_t)s * HID * RANK, tb, HID);
        convHL<<<(M * RANK / 4 + 255) / 256, 256>>>(tb, th, tl, (size_t)M * RANK / 4);
        convLU<<<(MLPD * 32 + 255) / 256, 256>>>(mlp0_lu + (size_t)s * RANK * MLPD, luh, lul, MLPD);
        launch_gemm(2, ah, al, w0h + s * MLP_SZ, w0l + s * MLP_SZ, th, tl, luh, lul,
                    mlp0_b + (size_t)s * MLPD, nullptr, nullptr, hb, M, MLPD, HID);

        convHL<<<(int)(((size_t)M * MLPD / 4 + 255) / 256), 256>>>(hb, ah, al, (size_t)M * MLPD / 4);
        tgemm2<<<M / 32, 256>>>(hb, mlp2_ld + (size_t)s * MLPD * RANK, tb, MLPD);
        convHL<<<(M * RANK / 4 + 255) / 256, 256>>>(tb, th, tl, (size_t)M * RANK / 4);
        convLU<<<(HID * 32 + 255) / 256, 256>>>(mlp2_lu + (size_t)s * RANK * HID, luh, lul, HID);
        launch_gemm(1, ah, al, w2h + s * MLP_SZ, w2l + s * MLP_SZ, th, tl, luh, lul,
                    mlp2_b + (size_t)s * HID, x1, mm + 5 * HID, outp, M, HID, MLPD);
    }
}

// round 5
// speedup vs baseline: 1.6653x; 1.1188x over previous
#include <cuda_runtime.h>
#include <cuda_bf16.h>
#include <math.h>

#define HID 3072
#define HEADS 24
#define HD 128
#define MLPD 12288
#define RANK 32
#define TXTL 512
#define IMGL 2048
#define L_TOT 2560
#define EPSF 1e-6f

#define QKV_SZ 28311552ULL
#define PRJ_SZ 9437184ULL
#define MLP_SZ 37748736ULL

// ---------------- device scratch ----------------
__device__ __align__(16) float g_sv[HID];
__device__ __align__(16) float g_mod[2 * 6 * HID];
__device__ __align__(16) float g_xm[(size_t)L_TOT * HID];
__device__ __align__(16) float g_t[(size_t)L_TOT * RANK];
__device__ __align__(16) float g_qkv[(size_t)L_TOT * 3 * HID];
__device__ __align__(16) float g_q[(size_t)L_TOT * HID];
__device__ __align__(16) float g_k[(size_t)L_TOT * HID];
__device__ __align__(16) float g_v[(size_t)L_TOT * HID];
__device__ __align__(16) float g_attn[(size_t)L_TOT * HID];
__device__ __align__(16) float g_x1[(size_t)L_TOT * HID];
__device__ __align__(16) float g_h[(size_t)IMGL * MLPD];

__device__ __align__(16) __nv_bfloat16 g_wq_h[2 * QKV_SZ], g_wq_l[2 * QKV_SZ];
__device__ __align__(16) __nv_bfloat16 g_wp_h[2 * PRJ_SZ], g_wp_l[2 * PRJ_SZ];
__device__ __align__(16) __nv_bfloat16 g_w0_h[2 * MLP_SZ], g_w0_l[2 * MLP_SZ];
__device__ __align__(16) __nv_bfloat16 g_w2_h[2 * MLP_SZ], g_w2_l[2 * MLP_SZ];
__device__ __align__(16) __nv_bfloat16 g_a_h[(size_t)IMGL * MLPD], g_a_l[(size_t)IMGL * MLPD];
__device__ __align__(16) __nv_bfloat16 g_t_h[(size_t)L_TOT * RANK], g_t_l[(size_t)L_TOT * RANK];
__device__ __align__(16) __nv_bfloat16 g_lu_h[(size_t)MLPD * RANK], g_lu_l[(size_t)MLPD * RANK];

// ---------------- asm helpers ----------------
__device__ __forceinline__ unsigned smem_u32(const void* p) {
    unsigned a;
    asm("{ .reg .u64 t; cvta.to.shared.u64 t, %1; cvt.u32.u64 %0, t; }" : "=r"(a) : "l"(p));
    return a;
}
__device__ __forceinline__ void ldmx4(unsigned (&r)[4], unsigned a) {
    asm volatile("ldmatrix.sync.aligned.m8n8.x4.shared.b16 {%0,%1,%2,%3}, [%4];"
                 : "=r"(r[0]), "=r"(r[1]), "=r"(r[2]), "=r"(r[3]) : "r"(a));
}
__device__ __forceinline__ void ldmx2(unsigned (&r)[2], unsigned a) {
    asm volatile("ldmatrix.sync.aligned.m8n8.x2.shared.b16 {%0,%1}, [%2];"
                 : "=r"(r[0]), "=r"(r[1]) : "r"(a));
}
__device__ __forceinline__ void mma16816(float (&d)[4], const unsigned (&a)[4], const unsigned (&b)[2]) {
    asm volatile("mma.sync.aligned.m16n8k16.row.col.f32.bf16.bf16.f32 "
                 "{%0,%1,%2,%3},{%4,%5,%6,%7},{%8,%9},{%0,%1,%2,%3};"
                 : "+f"(d[0]), "+f"(d[1]), "+f"(d[2]), "+f"(d[3])
                 : "r"(a[0]), "r"(a[1]), "r"(a[2]), "r"(a[3]), "r"(b[0]), "r"(b[1]));
}
__device__ __forceinline__ void cpa16(unsigned d, const void* s) {
    asm volatile("cp.async.cg.shared.global [%0], [%1], 16;" :: "r"(d), "l"(s));
}
__device__ __forceinline__ void cpcommit() { asm volatile("cp.async.commit_group;"); }
template <int N>
__device__ __forceinline__ void cpwait() { asm volatile("cp.async.wait_group %0;" :: "n"(N)); }

__device__ __forceinline__ float gelu2(float x) {
    float u = 0.7978845608028654f * (x + 0.044715f * x * x * x);
    float e = __expf(2.f * u);
    float th = 1.f - 2.f / (e + 1.f);
    return 0.5f * x * (1.f + th);
}

// ---------------- conversions ----------------
__global__ void __launch_bounds__(256) convHL(const float* __restrict__ src,
                                              __nv_bfloat16* __restrict__ dh,
                                              __nv_bfloat16* __restrict__ dl, size_t n4) {
    size_t idx = (size_t)blockIdx.x * 256 + threadIdx.x;
    if (idx >= n4) return;
    float4 v = ((const float4*)src)[idx];
    float vv[4] = {v.x, v.y, v.z, v.w};
    __nv_bfloat16 h[4], l[4];
#pragma unroll
    for (int i = 0; i < 4; ++i) {
        h[i] = __float2bfloat16(vv[i]);
        l[i] = __float2bfloat16(vv[i] - __bfloat162float(h[i]));
    }
    ((uint2*)dh)[idx] = *(uint2*)h;
    ((uint2*)dl)[idx] = *(uint2*)l;
}

__global__ void __launch_bounds__(256) convLU(const float* __restrict__ LU,
                                              __nv_bfloat16* __restrict__ dh,
                                              __nv_bfloat16* __restrict__ dl, int N) {
    int idx = blockIdx.x * 256 + threadIdx.x;
    if (idx >= N * 32) return;
    int n = idx >> 5, c = idx & 31;
    float v = LU[(size_t)c * N + n];
    __nv_bfloat16 h = __float2bfloat16(v);
    dh[(size_t)n * 32 + c] = h;
    dl[(size_t)n * 32 + c] = __float2bfloat16(v - __bfloat162float(h));
}

// ---------------- bf16 split-precision GEMM v2: 128x128 tile, 2 CTA/SM ----------------
// stage (pitch 80B): Ah 0, Al 10240, Bh 20480, Bl 30720 ; stage = 40960
#define STG_B 40960
#define GEMM_SMEM (2 * STG_B)

template <int MODE>
__global__ void __launch_bounds__(256, 2) gemm_mma(
    const __nv_bfloat16* __restrict__ Ah, const __nv_bfloat16* __restrict__ Al,
    const __nv_bfloat16* __restrict__ Bh, const __nv_bfloat16* __restrict__ Bl,
    const __nv_bfloat16* __restrict__ Th, const __nv_bfloat16* __restrict__ Tl,
    const __nv_bfloat16* __restrict__ LUh, const __nv_bfloat16* __restrict__ LUl,
    const float* __restrict__ bias, const float* __restrict__ RES,
    const float* __restrict__ GATE, float* __restrict__ C,
    int M, int N, int K) {
    extern __shared__ char sm[];
    unsigned sbase = smem_u32(sm);
    int tid = threadIdx.x, lane = tid & 31, wid = tid >> 5;
    int wm = wid >> 2, wn = wid & 3;
    int bm = blockIdx.x * 128, bn = blockIdx.y * 128;
    int KC = K >> 5, TOT = KC + 1;

    float acc[4][4][4];
#pragma unroll
    for (int a = 0; a < 4; ++a)
#pragma unroll
        for (int b = 0; b < 4; ++b)
#pragma unroll
            for (int c = 0; c < 4; ++c) acc[a][b][c] = 0.f;

#define LOAD_STAGE(cc)                                                                   \
    {                                                                                    \
        int c_ = (cc);                                                                   \
        unsigned sb_ = sbase + (c_ & 1) * STG_B;                                         \
        const __nv_bfloat16* bases_[4];                                                  \
        size_t st_; int ko_;                                                             \
        if (c_ < KC) { bases_[0] = Ah; bases_[1] = Al; bases_[2] = Bh; bases_[3] = Bl;   \
                       st_ = K; ko_ = c_ * 32; }                                         \
        else { bases_[0] = Th; bases_[1] = Tl; bases_[2] = LUh; bases_[3] = LUl;         \
               st_ = 32; ko_ = 0; }                                                      \
        _Pragma("unroll")                                                                \
        for (int j = 0; j < 8; ++j) {                                                    \
            int i = tid + j * 256;                                                       \
            int mat = i >> 9, r = (i >> 2) & 127, seg = i & 3;                           \
            int gr = (mat < 2 ? bm : bn) + r;                                            \
            const __nv_bfloat16* s_ = bases_[mat] + (size_t)gr * st_ + ko_ + seg * 8;    \
            cpa16(sb_ + mat * 10240 + r * 80 + seg * 16, s_);                            \
        }                                                                                \
        cpcommit();                                                                      \
    }

    LOAD_STAGE(0);
    for (int c = 0; c < TOT; ++c) {
        if (c + 1 < TOT) { LOAD_STAGE(c + 1); cpwait<1>(); }
        else { cpwait<0>(); }
        __syncthreads();
        unsigned sb = sbase + (c & 1) * STG_B;
#pragma unroll
        for (int s = 0; s < 2; ++s) {
            unsigned ahf[4][4], alf[4][4];
#pragma unroll
            for (int mf = 0; mf < 4; ++mf) {
                unsigned row = wm * 64 + mf * 16 + (lane & 15);
                unsigned off = row * 80 + s * 32 + ((lane >> 4) << 4);
                ldmx4(ahf[mf], sb + off);
                ldmx4(alf[mf], sb + 10240 + off);
            }
#pragma unroll
            for (int nf = 0; nf < 4; ++nf) {
                unsigned brow = wn * 32 + nf * 8 + (lane & 7);
                unsigned boff = 20480 + brow * 80 + s * 32 + (((lane >> 3) & 1) << 4);
                unsigned bh2[2], bl2[2];
                ldmx2(bh2, sb + boff);
                ldmx2(bl2, sb + 10240 + boff);
#pragma unroll
                for (int mf = 0; mf < 4; ++mf) {
                    mma16816(acc[mf][nf], ahf[mf], bh2);
                    mma16816(acc[mf][nf], ahf[mf], bl2);
                    mma16816(acc[mf][nf], alf[mf], bh2);
                }
            }
        }
        __syncthreads();
    }

    // epilogue
#pragma unroll
    for (int nf = 0; nf < 4; ++nf) {
        int gn = bn + wn * 32 + nf * 8 + (lane & 3) * 2;
        float b0 = bias[gn], b1 = bias[gn + 1];
        float g0 = 0.f, g1 = 0.f;
        if (MODE == 1) { g0 = GATE[gn]; g1 = GATE[gn + 1]; }
#pragma unroll
        for (int mf = 0; mf < 4; ++mf) {
            int gm = bm + wm * 64 + mf * 16 + (lane >> 2);
            float v0 = acc[mf][nf][0] + b0, v1 = acc[mf][nf][1] + b1;
            float v2 = acc[mf][nf][2] + b0, v3 = acc[mf][nf][3] + b1;
            if (MODE == 2) { v0 = gelu2(v0); v1 = gelu2(v1); v2 = gelu2(v2); v3 = gelu2(v3); }
            if (MODE == 1) {
                float2 r0 = *(const float2*)&RES[(size_t)gm * N + gn];
                float2 r1 = *(const float2*)&RES[(size_t)(gm + 8) * N + gn];
                v0 = r0.x + g0 * v0; v1 = r0.y + g1 * v1;
                v2 = r1.x + g0 * v2; v3 = r1.y + g1 * v3;
            }
            *(float2*)&C[(size_t)gm * N + gn] = make_float2(v0, v1);
            *(float2*)&C[(size_t)(gm + 8) * N + gn] = make_float2(v2, v3);
        }
    }
}

// ---------------- small kernels ----------------
__device__ __forceinline__ void blockReduce2(float& a, float& b, float* sbuf) {
    int lane = threadIdx.x & 31, w = threadIdx.x >> 5;
    int nw = blockDim.x >> 5;
#pragma unroll
    for (int o = 16; o; o >>= 1) {
        a += __shfl_xor_sync(0xffffffffu, a, o);
        b += __shfl_xor_sync(0xffffffffu, b, o);
    }
    if (lane == 0) { sbuf[w] = a; sbuf[nw + w] = b; }
    __syncthreads();
    a = 0.f; b = 0.f;
    for (int i = 0; i < nw; ++i) { a += sbuf[i]; b += sbuf[nw + i]; }
    __syncthreads();
}

__global__ void silu_kernel(const float* __restrict__ v, float* __restrict__ o) {
    int i = blockIdx.x * 256 + threadIdx.x;
    if (i < HID) { float x = v[i]; o[i] = x / (1.f + __expf(-x)); }
}

__global__ void __launch_bounds__(128) gemv_mod(const float* __restrict__ w,
                                                const float* __restrict__ b,
                                                const float* __restrict__ sv,
                                                float* __restrict__ o) {
    __shared__ float sbuf[8];
    int n = blockIdx.x;
    const float4* wr = (const float4*)(w + (size_t)n * HID);
    const float4* vv = (const float4*)sv;
    int t = threadIdx.x;
    float s = 0.f;
#pragma unroll
    for (int i = 0; i < 6; ++i) {
        float4 a = wr[t + i * 128], c = vv[t + i * 128];
        s += a.x * c.x + a.y * c.y + a.z * c.z + a.w * c.w;
    }
    float dummy = 0.f;
    blockReduce2(s, dummy, sbuf);
    if (t == 0) o[n] = s + b[n];
}

__global__ void __launch_bounds__(256) ln_mod(const float* __restrict__ x,
                                              const float* __restrict__ sh,
                                              const float* __restrict__ sc,
                                              float* __restrict__ o) {
    __shared__ float sbuf[16];
    int row = blockIdx.x, t = threadIdx.x;
    const float4* xr = (const float4*)(x + (size_t)row * HID);
    float4 v[3];
    float s = 0.f, s2 = 0.f;
#pragma unroll
    for (int i = 0; i < 3; ++i) {
        v[i] = xr[t + i * 256];
        s += v[i].x + v[i].y + v[i].z + v[i].w;
        s2 += v[i].x * v[i].x + v[i].y * v[i].y + v[i].z * v[i].z + v[i].w * v[i].w;
    }
    blockReduce2(s, s2, sbuf);
    float mean = s * (1.f / HID);
    float var = s2 * (1.f / HID) - mean * mean;
    float rstd = rsqrtf(var + EPSF);
    float4* orow = (float4*)(o + (size_t)row * HID);
    const float4* sh4 = (const float4*)sh;
    const float4* sc4 = (const float4*)sc;
#pragma unroll
    for (int i = 0; i < 3; ++i) {
        int c = t + i * 256;
        float4 scv = sc4[c], shv = sh4[c], r;
        r.x = (v[i].x - mean) * rstd * (1.f + scv.x) + shv.x;
        r.y = (v[i].y - mean) * rstd * (1.f + scv.y) + shv.y;
        r.z = (v[i].z - mean) * rstd * (1.f + scv.z) + shv.z;
        r.w = (v[i].w - mean) * rstd * (1.f + scv.w) + shv.w;
        orow[c] = r;
    }
}

__global__ void __launch_bounds__(256) tgemm2(const float* __restrict__ A,
                                              const float* __restrict__ LD,
                                              float* __restrict__ T, int K) {
    __shared__ float Ls[64 * 32];
    __shared__ float As[32 * 68];
    int tid = threadIdx.x, lane = tid & 31, w = tid >> 5;
    int bm = blockIdx.x * 32;
    float acc[4] = {0.f, 0.f, 0.f, 0.f};
    for (int k0 = 0; k0 < K; k0 += 64) {
        __syncthreads();
#pragma unroll
        for (int j = 0; j < 8; ++j) {
            int i = tid + j * 256;
            Ls[i] = LD[(size_t)(k0 + (i >> 5)) * 32 + (i & 31)];
        }
#pragma unroll
        for (int j = 0; j < 8; ++j) {
            int i = tid + j * 256;
            int r = i >> 6, c = i & 63;
            As[r * 68 + c] = A[(size_t)(bm + r) * K + k0 + c];
        }
        __syncthreads();
#pragma unroll 8
        for (int kk = 0; kk < 64; ++kk) {
            float ldv = Ls[kk * 32 + lane];
#pragma unroll
            for (int i = 0; i < 4; ++i) acc[i] += As[(w * 4 + i) * 68 + kk] * ldv;
        }
    }
#pragma unroll
    for (int i = 0; i < 4; ++i) T[(size_t)(bm + w * 4 + i) * 32 + lane] = acc[i];
}

__global__ void __launch_bounds__(64) rmsrope(const float* __restrict__ qkv,
                                              const float* __restrict__ wq,
                                              const float* __restrict__ wk,
                                              const float* __restrict__ pe, int loff,
                                              float* __restrict__ Q, float* __restrict__ K,
                                              float* __restrict__ V) {
    __shared__ float sbuf[4];
    int row = blockIdx.x, h = blockIdx.y, p = threadIdx.x;
    int l = loff + row;
    const float* base = qkv + (size_t)row * (3 * HID) + h * HD;
    float q0 = base[2 * p], q1 = base[2 * p + 1];
    float k0 = base[HID + 2 * p], k1 = base[HID + 2 * p + 1];
    float sq = q0 * q0 + q1 * q1, sk = k0 * k0 + k1 * k1;
#pragma unroll
    for (int o = 16; o; o >>= 1) {
        sq += __shfl_xor_sync(0xffffffffu, sq, o);
        sk += __shfl_xor_sync(0xffffffffu, sk, o);
    }
    int w = p >> 5;
    if ((p & 31) == 0) { sbuf[w] = sq; sbuf[2 + w] = sk; }
    __syncthreads();
    sq = sbuf[0] + sbuf[1];
    sk = sbuf[2] + sbuf[3];
    float rq = rsqrtf(sq * (1.f / HD) + EPSF);
    float rk = rsqrtf(sk * (1.f / HD) + EPSF);
    q0 *= rq * wq[2 * p]; q1 *= rq * wq[2 * p + 1];
    k0 *= rk * wk[2 * p]; k1 *= rk * wk[2 * p + 1];
    float4 f = ((const float4*)(pe + (size_t)l * 256))[p];
    size_t ob = (size_t)l * HID + h * HD;
    Q[ob + 2 * p] = f.x * q0 + f.y * q1;
    Q[ob + 2 * p + 1] = f.z * q0 + f.w * q1;
    K[ob + 2 * p] = f.x * k0 + f.y * k1;
    K[ob + 2 * p + 1] = f.z * k0 + f.w * k1;
    V[ob + 2 * p] = base[2 * HID + 2 * p];
    V[ob + 2 * p + 1] = base[2 * HID + 2 * p + 1];
}

#define FLASH_SMEM ((3 * 64 * 132 + 64 * 65) * 4)
__global__ void __launch_bounds__(256) flash(const float* __restrict__ Qg,
                                             const float* __restrict__ Kg,
                                             const float* __restrict__ Vg,
                                             float* __restrict__ Og) {
    extern __shared__ float smf[];
    float* Qs = smf;
    float* Ks = Qs + 64 * 132;
    float* Vs = Ks + 64 * 132;
    float* Ps = Vs + 64 * 132;
    int h = blockIdx.y;
    int qb = blockIdx.x * 64;
    int t = threadIdx.x, r = t >> 2, g = t & 3;
    const float scale = 0.08838834764831845f;

    for (int i = t; i < 64 * 32; i += 256) {
        int rr = i >> 5, c = i & 31;
        float4 qv = ((const float4*)(Qg + (size_t)(qb + rr) * HID + h * HD))[c];
        qv.x *= scale; qv.y *= scale; qv.z *= scale; qv.w *= scale;
        ((float4*)Qs)[rr * 33 + c] = qv;
    }
    float m = -1e30f, lsum = 0.f;
    float4 acc[8];
#pragma unroll
    for (int w = 0; w < 8; ++w) acc[w] = make_float4(0.f, 0.f, 0.f, 0.f);

    for (int kt = 0; kt < L_TOT; kt += 64) {
        __syncthreads();
        for (int i = t; i < 64 * 32; i += 256) {
            int rr = i >> 5, c = i & 31;
            ((float4*)Ks)[rr * 33 + c] = ((const float4*)(Kg + (size_t)(kt + rr) * HID + h * HD))[c];
            ((float4*)Vs)[rr * 33 + c] = ((const float4*)(Vg + (size_t)(kt + rr) * HID + h * HD))[c];
        }
        __syncthreads();

        float s[16];
#pragma unroll
        for (int jj = 0; jj < 16; ++jj) s[jj] = 0.f;
#pragma unroll 8
        for (int d4 = 0; d4 < 32; ++d4) {
            float4 qv = ((const float4*)Qs)[r * 33 + d4];
#pragma unroll
            for (int jj = 0; jj < 16; ++jj) {
                float4 kv = ((const float4*)Ks)[(g + 4 * jj) * 33 + d4];
                s[jj] += qv.x * kv.x + qv.y * kv.y + qv.z * kv.z + qv.w * kv.w;
            }
        }
        float tm = s[0];
#pragma unroll
        for (int jj = 1; jj < 16; ++jj) tm = fmaxf(tm, s[jj]);
        tm = fmaxf(tm, __shfl_xor_sync(0xffffffffu, tm, 1));
        tm = fmaxf(tm, __shfl_xor_sync(0xffffffffu, tm, 2));
        float mn = fmaxf(m, tm);
        float corr = __expf(m - mn);
        float ps = 0.f;
#pragma unroll
        for (int jj = 0; jj < 16; ++jj) {
            float pv = __expf(s[jj] - mn);
            Ps[r * 65 + g + 4 * jj] = pv;
            ps += pv;
        }
        ps += __shfl_xor_sync(0xffffffffu, ps, 1);
        ps += __shfl_xor_sync(0xffffffffu, ps, 2);
        lsum = lsum * corr + ps;
        m = mn;
#pragma unroll
        for (int w = 0; w < 8; ++w) {
            acc[w].x *= corr; acc[w].y *= corr; acc[w].z *= corr; acc[w].w *= corr;
        }
        __syncthreads();
#pragma unroll 4
        for (int j = 0; j < 64; ++j) {
            float pv = Ps[r * 65 + j];
#pragma unroll
            for (int w = 0; w < 8; ++w) {
                float4 vv = ((const float4*)Vs)[j * 33 + g + 4 * w];
                acc[w].x += pv * vv.x; acc[w].y += pv * vv.y;
                acc[w].z += pv * vv.z; acc[w].w += pv * vv.w;
            }
        }
    }
    float inv = 1.f / lsum;
#pragma unroll
    for (int w = 0; w < 8; ++w) {
        float4 o;
        o.x = acc[w].x * inv; o.y = acc[w].y * inv;
        o.z = acc[w].z * inv; o.w = acc[w].w * inv;
        ((float4*)(Og + (size_t)(qb + r) * HID + h * HD))[g + 4 * w] = o;
    }
}

// ---------------- host ----------------
static inline void launch_gemm(int mode, const __nv_bfloat16* Ah, const __nv_bfloat16* Al,
                               const __nv_bfloat16* Bh, const __nv_bfloat16* Bl,
                               const __nv_bfloat16* Th, const __nv_bfloat16* Tl,
                               const __nv_bfloat16* LUh, const __nv_bfloat16* LUl,
                               const float* bias, const float* RES, const float* GATE,
                               float* C, int M, int N, int K) {
    dim3 g(M / 128, N / 128);
    if (mode == 0)
        gemm_mma<0><<<g, 256, GEMM_SMEM>>>(Ah, Al, Bh, Bl, Th, Tl, LUh, LUl, bias, RES, GATE, C, M, N, K);
    else if (mode == 1)
        gemm_mma<1><<<g, 256, GEMM_SMEM>>>(Ah, Al, Bh, Bl, Th, Tl, LUh, LUl, bias, RES, GATE, C, M, N, K);
    else
        gemm_mma<2><<<g, 256, GEMM_SMEM>>>(Ah, Al, Bh, Bl, Th, Tl, LUh, LUl, bias, RES, GATE, C, M, N, K);
}

extern "C" void kernel_launch(void* const* d_in, const int* in_sizes, int n_in,
                              void* d_out, int out_size) {
    const float* img = (const float*)d_in[0];
    const float* txt = (const float*)d_in[1];
    const float* vec = (const float*)d_in[2];
    const float* pe = (const float*)d_in[3];
    const float* mod_w = (const float*)d_in[4];
    const float* mod_b = (const float*)d_in[5];
    const float* qkv_w = (const float*)d_in[6];
    const float* qkv_b = (const float*)d_in[7];
    const float* qkv_ld = (const float*)d_in[8];
    const float* qkv_lu = (const float*)d_in[9];
    const float* rmsq_w = (const float*)d_in[10];
    const float* rmsk_w = (const float*)d_in[11];
    const float* proj_w = (const float*)d_in[12];
    const float* proj_b = (const float*)d_in[13];
    const float* proj_ld = (const float*)d_in[14];
    const float* proj_lu = (const float*)d_in[15];
    const float* mlp0_w = (const float*)d_in[16];
    const float* mlp0_b = (const float*)d_in[17];
    const float* mlp0_ld = (const float*)d_in[18];
    const float* mlp0_lu = (const float*)d_in[19];
    const float* mlp2_w = (const float*)d_in[20];
    const float* mlp2_b = (const float*)d_in[21];
    const float* mlp2_ld = (const float*)d_in[22];
    const float* mlp2_lu = (const float*)d_in[23];
    float* out = (float*)d_out;

    float *sv, *mod, *xm, *tb, *qkv, *q, *k, *v, *attn, *x1, *hb;
    __nv_bfloat16 *wqh, *wql, *wph, *wpl, *w0h, *w0l, *w2h, *w2l;
    __nv_bfloat16 *ah, *al, *th, *tl, *luh, *lul;
    cudaGetSymbolAddress((void**)&sv, g_sv);
    cudaGetSymbolAddress((void**)&mod, g_mod);
    cudaGetSymbolAddress((void**)&xm, g_xm);
    cudaGetSymbolAddress((void**)&tb, g_t);
    cudaGetSymbolAddress((void**)&qkv, g_qkv);
    cudaGetSymbolAddress((void**)&q, g_q);
    cudaGetSymbolAddress((void**)&k, g_k);
    cudaGetSymbolAddress((void**)&v, g_v);
    cudaGetSymbolAddress((void**)&attn, g_attn);
    cudaGetSymbolAddress((void**)&x1, g_x1);
    cudaGetSymbolAddress((void**)&hb, g_h);
    cudaGetSymbolAddress((void**)&wqh, g_wq_h);
    cudaGetSymbolAddress((void**)&wql, g_wq_l);
    cudaGetSymbolAddress((void**)&wph, g_wp_h);
    cudaGetSymbolAddress((void**)&wpl, g_wp_l);
    cudaGetSymbolAddress((void**)&w0h, g_w0_h);
    cudaGetSymbolAddress((void**)&w0l, g_w0_l);
    cudaGetSymbolAddress((void**)&w2h, g_w2_h);
    cudaGetSymbolAddress((void**)&w2l, g_w2_l);
    cudaGetSymbolAddress((void**)&ah, g_a_h);
    cudaGetSymbolAddress((void**)&al, g_a_l);
    cudaGetSymbolAddress((void**)&th, g_t_h);
    cudaGetSymbolAddress((void**)&tl, g_t_l);
    cudaGetSymbolAddress((void**)&luh, g_lu_h);
    cudaGetSymbolAddress((void**)&lul, g_lu_l);

    cudaFuncSetAttribute(flash, cudaFuncAttributeMaxDynamicSharedMemorySize, FLASH_SMEM);
    cudaFuncSetAttribute(gemm_mma<0>, cudaFuncAttributeMaxDynamicSharedMemorySize, GEMM_SMEM);
    cudaFuncSetAttribute(gemm_mma<1>, cudaFuncAttributeMaxDynamicSharedMemorySize, GEMM_SMEM);
    cudaFuncSetAttribute(gemm_mma<2>, cudaFuncAttributeMaxDynamicSharedMemorySize, GEMM_SMEM);

    silu_kernel<<<(HID + 255) / 256, 256>>>(vec, sv);
    gemv_mod<<<2 * 6 * HID, 128>>>(mod_w, mod_b, sv, mod);

    convHL<<<(int)((2 * QKV_SZ / 4 + 255) / 256), 256>>>(qkv_w, wqh, wql, 2 * QKV_SZ / 4);
    convHL<<<(int)((2 * PRJ_SZ / 4 + 255) / 256), 256>>>(proj_w, wph, wpl, 2 * PRJ_SZ / 4);
    convHL<<<(int)((2 * MLP_SZ / 4 + 255) / 256), 256>>>(mlp0_w, w0h, w0l, 2 * MLP_SZ / 4);
    convHL<<<(int)((2 * MLP_SZ / 4 + 255) / 256), 256>>>(mlp2_w, w2h, w2l, 2 * MLP_SZ / 4);

    for (int s = 0; s < 2; ++s) {
        const float* x = s == 0 ? img : txt;
        int M = s == 0 ? IMGL : TXTL;
        int loff = s == 0 ? TXTL : 0;
        const float* mm = mod + (size_t)s * 6 * HID;
        ln_mod<<<M, 256>>>(x, mm + 0 * HID, mm + 1 * HID, xm);
        convHL<<<(M * HID / 4 + 255) / 256, 256>>>(xm, ah, al, (size_t)M * HID / 4);
        tgemm2<<<M / 32, 256>>>(xm, qkv_ld + (size_t)s * HID * RANK, tb, HID);
        convHL<<<(M * RANK / 4 + 255) / 256, 256>>>(tb, th, tl, (size_t)M * RANK / 4);
        convLU<<<(9216 * 32 + 255) / 256, 256>>>(qkv_lu + (size_t)s * RANK * 9216, luh, lul, 9216);
        launch_gemm(0, ah, al, wqh + s * QKV_SZ, wql + s * QKV_SZ, th, tl, luh, lul,
                    qkv_b + (size_t)s * 9216, nullptr, nullptr, qkv, M, 9216, HID);
        dim3 g2(M, HEADS);
        rmsrope<<<g2, 64>>>(qkv, rmsq_w + (size_t)s * HD, rmsk_w + (size_t)s * HD, pe, loff, q, k, v);
    }

    dim3 gf(L_TOT / 64, HEADS);
    flash<<<gf, 256, FLASH_SMEM>>>(q, k, v, attn);

    for (int s = 0; s < 2; ++s) {
        const float* x = s == 0 ? img : txt;
        int M = s == 0 ? IMGL : TXTL;
        int roff = s == 0 ? TXTL : 0;
        const float* a = attn + (size_t)roff * HID;
        const float* mm = mod + (size_t)s * 6 * HID;
        float* outp = out + (size_t)roff * HID;

        convHL<<<(M * HID / 4 + 255) / 256, 256>>>(a, ah, al, (size_t)M * HID / 4);
        tgemm2<<<M / 32, 256>>>(a, proj_ld + (size_t)s * HID * RANK, tb, HID);
        convHL<<<(M * RANK / 4 + 255) / 256, 256>>>(tb, th, tl, (size_t)M * RANK / 4);
        convLU<<<(HID * 32 + 255) / 256, 256>>>(proj_lu + (size_t)s * RANK * HID, luh, lul, HID);
        launch_gemm(1, ah, al, wph + s * PRJ_SZ, wpl + s * PRJ_SZ, th, tl, luh, lul,
                    proj_b + (size_t)s * HID, x, mm + 2 * HID, x1, M, HID, HID);

        ln_mod<<<M, 256>>>(x1, mm + 3 * HID, mm + 4 * HID, xm);
        convHL<<<(M * HID / 4 + 255) / 256, 256>>>(xm, ah, al, (size_t)M * HID / 4);
        tgemm2<<<M / 32, 256>>>(xm, mlp0_ld + (size_t)s * HID * RANK, tb, HID);
        convHL<<<(M * RANK / 4 + 255) / 256, 256>>>(tb, th, tl, (size_t)M * RANK / 4);
        convLU<<<(MLPD * 32 + 255) / 256, 256>>>(mlp0_lu + (size_t)s * RANK * MLPD, luh, lul, MLPD);
        launch_gemm(2, ah, al, w0h + s * MLP_SZ, w0l + s * MLP_SZ, th, tl, luh, lul,
                    mlp0_b + (size_t)s * MLPD, nullptr, nullptr, hb, M, MLPD, HID);

        convHL<<<(int)(((size_t)M * MLPD / 4 + 255) / 256), 256>>>(hb, ah, al, (size_t)M * MLPD / 4);
        tgemm2<<<M / 32, 256>>>(hb, mlp2_ld + (size_t)s * MLPD * RANK, tb, MLPD);
        convHL<<<(M * RANK / 4 + 255) / 256, 256>>>(tb, th, tl, (size_t)M * RANK / 4);
        convLU<<<(HID * 32 + 255) / 256, 256>>>(mlp2_lu + (size_t)s * RANK * HID, luh, lul, HID);
        launch_gemm(1, ah, al, w2h + s * MLP_SZ, w2l + s * MLP_SZ, th, tl, luh, lul,
                    mlp2_b + (size_t)s * HID, x1, mm + 5 * HID, outp, M, HID, MLPD);
    }
}